// round 2
// baseline (speedup 1.0000x reference)
#include <cuda_runtime.h>

#define N_ROWS 65536
#define D 64
#define R 256
#define DV 64
#define NORM 0.35355339059327379f   // 64^-0.25
#define RATIO 0.0625f               // 256^-0.5

#define ROWS_K 128
#define KTILES (N_ROWS / ROWS_K)    // 512
#define KBLOCKS 148
#define ROWS_Q 64
#define QTILES (N_ROWS / ROWS_Q)    // 1024

#define QH_STRIDE (R + 4)           // pad so 4-row-apart banks differ

// scratch (allocation-free rule: device globals)
__device__ float g_z[R * DV];
__device__ float g_ksum[R];

__global__ void zero_kernel() {
    int t = blockIdx.x * blockDim.x + threadIdx.x;
    if (t < R * DV) g_z[t] = 0.0f;
    if (t < R) g_ksum[t] = 0.0f;
}

// ---------------- K side: z = k_hat^T @ v, ksum = sum_i k_hat[i,:] -------------
__global__ __launch_bounds__(256, 1) void kside_kernel(
    const float* __restrict__ kin, const float* __restrict__ vin,
    const float* __restrict__ proj)
{
    extern __shared__ float smem[];
    float* kn = smem;                      // ROWS_K * D
    float* vs = kn + ROWS_K * D;           // ROWS_K * DV
    float* sn = vs + ROWS_K * DV;          // ROWS_K

    const int t = threadIdx.x;             // 0..255 <-> feature r

    float p[D];
#pragma unroll
    for (int j = 0; j < D; j += 4) {
        float4 f = *reinterpret_cast<const float4*>(&proj[t * D + j]);
        p[j] = f.x; p[j + 1] = f.y; p[j + 2] = f.z; p[j + 3] = f.w;
    }

    float zacc[DV];
#pragma unroll
    for (int c = 0; c < DV; c++) zacc[c] = 0.0f;
    float ksacc = 0.0f;

    for (int tile = blockIdx.x; tile < KTILES; tile += gridDim.x) {
        __syncthreads();
        const float4* kb = reinterpret_cast<const float4*>(kin + (size_t)tile * ROWS_K * D);
        const float4* vb = reinterpret_cast<const float4*>(vin + (size_t)tile * ROWS_K * DV);
#pragma unroll
        for (int m = 0; m < (ROWS_K * D / 4) / 256; m++) {   // 8 iters
            int idx = t + 256 * m;
            float4 a = kb[idx];
            a.x *= NORM; a.y *= NORM; a.z *= NORM; a.w *= NORM;
            *reinterpret_cast<float4*>(&kn[idx * 4]) = a;
            float ps = a.x * a.x + a.y * a.y + a.z * a.z + a.w * a.w;
            // 16 consecutive lanes hold the 16 float4s of one row
#pragma unroll
            for (int s = 8; s >= 1; s >>= 1)
                ps += __shfl_xor_sync(0xffffffffu, ps, s);
            if ((t & 15) == 0) sn[idx >> 4] = ps;
            *reinterpret_cast<float4*>(&vs[idx * 4]) = vb[idx];
        }
        __syncthreads();

        for (int i = 0; i < ROWS_K; i++) {
            float dash = 0.0f;
#pragma unroll
            for (int j = 0; j < D; j += 4) {
                float4 a = *reinterpret_cast<const float4*>(&kn[i * D + j]);
                dash += a.x * p[j] + a.y * p[j + 1] + a.z * p[j + 2] + a.w * p[j + 3];
            }
            float kh = RATIO * __expf(dash - 0.5f * sn[i]);
            ksacc += kh;
#pragma unroll
            for (int c = 0; c < DV; c += 4) {
                float4 vv = *reinterpret_cast<const float4*>(&vs[i * DV + c]);
                zacc[c]     += kh * vv.x;
                zacc[c + 1] += kh * vv.y;
                zacc[c + 2] += kh * vv.z;
                zacc[c + 3] += kh * vv.w;
            }
        }
    }

    atomicAdd(&g_ksum[t], ksacc);
#pragma unroll
    for (int c = 0; c < DV; c++)
        atomicAdd(&g_z[t * DV + c], zacc[c]);
}

// ---------------- Q side: out = (q_hat @ z) / (q_hat . ksum) ------------------
__global__ __launch_bounds__(256, 1) void qside_kernel(
    const float* __restrict__ qin, const float* __restrict__ proj,
    float* __restrict__ out)
{
    extern __shared__ float smem[];
    float* zsh  = smem;                          // R*DV          = 16384 f
    float* qh   = zsh + R * DV;                  // ROWS_Q*QH_STRIDE = 16640 f
    float* qn   = qh + ROWS_Q * QH_STRIDE;       // ROWS_Q*D      = 4096 f
    float* sn   = qn + ROWS_Q * D;               // ROWS_Q
    float* ks   = sn + ROWS_Q;                   // R
    float* dinv = ks + R;                        // ROWS_Q

    const int t = threadIdx.x;

    float p[D];
#pragma unroll
    for (int j = 0; j < D; j += 4) {
        float4 f = *reinterpret_cast<const float4*>(&proj[t * D + j]);
        p[j] = f.x; p[j + 1] = f.y; p[j + 2] = f.z; p[j + 3] = f.w;
    }

    // stage z + ksum into shared
#pragma unroll
    for (int m = 0; m < (R * DV / 4) / 256; m++) {   // 16 iters
        int idx = t + 256 * m;
        *reinterpret_cast<float4*>(&zsh[idx * 4]) =
            *reinterpret_cast<const float4*>(&g_z[idx * 4]);
    }
    ks[t] = g_ksum[t];

    const int tile = blockIdx.x;
    const float4* qb = reinterpret_cast<const float4*>(qin + (size_t)tile * ROWS_Q * D);
#pragma unroll
    for (int m = 0; m < (ROWS_Q * D / 4) / 256; m++) {  // 4 iters
        int idx = t + 256 * m;
        float4 a = qb[idx];
        a.x *= NORM; a.y *= NORM; a.z *= NORM; a.w *= NORM;
        *reinterpret_cast<float4*>(&qn[idx * 4]) = a;
        float ps = a.x * a.x + a.y * a.y + a.z * a.z + a.w * a.w;
#pragma unroll
        for (int s = 8; s >= 1; s >>= 1)
            ps += __shfl_xor_sync(0xffffffffu, ps, s);
        if ((t & 15) == 0) sn[idx >> 4] = ps;
    }
    __syncthreads();

    // phase 1: qh[i][t] = ratio * exp(dash - 0.5*sn)
    for (int i = 0; i < ROWS_Q; i++) {
        float dash = 0.0f;
#pragma unroll
        for (int j = 0; j < D; j += 4) {
            float4 a = *reinterpret_cast<const float4*>(&qn[i * D + j]);
            dash += a.x * p[j] + a.y * p[j + 1] + a.z * p[j + 2] + a.w * p[j + 3];
        }
        qh[i * QH_STRIDE + t] = RATIO * __expf(dash - 0.5f * sn[i]);
    }
    __syncthreads();

    // denominators: warp w -> rows w*8 .. w*8+7
    {
        int w = t >> 5, l = t & 31;
#pragma unroll
        for (int ii = 0; ii < 8; ii++) {
            int i = w * 8 + ii;
            float s = 0.0f;
#pragma unroll
            for (int kk = 0; kk < R / 32; kk++)
                s += qh[i * QH_STRIDE + l + 32 * kk] * ks[l + 32 * kk];
#pragma unroll
            for (int sd = 16; sd >= 1; sd >>= 1)
                s += __shfl_xor_sync(0xffffffffu, s, sd);
            if (l == 0) dinv[i] = 1.0f / s;
        }
    }
    __syncthreads();

    // phase 2: 4x4 register-tiled GEMM qh[64x256] @ zsh[256x64]
    {
        const int bc = t & 15;       // column block
        const int bi = t >> 4;       // row block
        const int i0 = bi * 4;
        const int c0 = bc * 4;
        float acc[4][4];
#pragma unroll
        for (int a = 0; a < 4; a++)
#pragma unroll
            for (int b = 0; b < 4; b++) acc[a][b] = 0.0f;

#pragma unroll 4
        for (int r = 0; r < R; r++) {
            float4 zv = *reinterpret_cast<const float4*>(&zsh[r * DV + c0]);
            float q0 = qh[(i0 + 0) * QH_STRIDE + r];
            float q1 = qh[(i0 + 1) * QH_STRIDE + r];
            float q2 = qh[(i0 + 2) * QH_STRIDE + r];
            float q3 = qh[(i0 + 3) * QH_STRIDE + r];
            acc[0][0] += q0 * zv.x; acc[0][1] += q0 * zv.y; acc[0][2] += q0 * zv.z; acc[0][3] += q0 * zv.w;
            acc[1][0] += q1 * zv.x; acc[1][1] += q1 * zv.y; acc[1][2] += q1 * zv.z; acc[1][3] += q1 * zv.w;
            acc[2][0] += q2 * zv.x; acc[2][1] += q2 * zv.y; acc[2][2] += q2 * zv.z; acc[2][3] += q2 * zv.w;
            acc[3][0] += q3 * zv.x; acc[3][1] += q3 * zv.y; acc[3][2] += q3 * zv.z; acc[3][3] += q3 * zv.w;
        }

        float* ob = out + (size_t)tile * ROWS_Q * DV;
#pragma unroll
        for (int a = 0; a < 4; a++) {
            float di = dinv[i0 + a];
            float4 o;
            o.x = acc[a][0] * di; o.y = acc[a][1] * di;
            o.z = acc[a][2] * di; o.w = acc[a][3] * di;
            *reinterpret_cast<float4*>(&ob[(i0 + a) * DV + c0]) = o;
        }
    }
}

extern "C" void kernel_launch(void* const* d_in, const int* in_sizes, int n_in,
                              void* d_out, int out_size) {
    const float* q = (const float*)d_in[0];
    const float* k = (const float*)d_in[1];
    const float* v = (const float*)d_in[2];
    const float* P = (const float*)d_in[3];
    float* out = (float*)d_out;
    (void)in_sizes; (void)n_in; (void)out_size;

    const int ksmem = (ROWS_K * D + ROWS_K * DV + ROWS_K) * (int)sizeof(float);
    const int qsmem = (R * DV + ROWS_Q * QH_STRIDE + ROWS_Q * D + ROWS_Q + R + ROWS_Q)
                      * (int)sizeof(float);

    cudaFuncSetAttribute(kside_kernel, cudaFuncAttributeMaxDynamicSharedMemorySize, ksmem);
    cudaFuncSetAttribute(qside_kernel, cudaFuncAttributeMaxDynamicSharedMemorySize, qsmem);

    zero_kernel<<<64, 256>>>();
    kside_kernel<<<KBLOCKS, 256, ksmem>>>(k, v, P);
    qside_kernel<<<QTILES, 256, qsmem>>>(q, P, out);
}

// round 3
// speedup vs baseline: 1.1246x; 1.1246x over previous
#include <cuda_runtime.h>

#define N_ROWS 65536
#define D 64
#define R 256
#define DV 64
#define NORM 0.35355339059327379f   // 64^-0.25
#define RATIO 0.0625f               // 256^-0.5

#define ROWS_K 128
#define KTILES (N_ROWS / ROWS_K)    // 512
#define KBLOCKS 148
#define ROWS_Q 64
#define QTILES (N_ROWS / ROWS_Q)    // 1024

#define QH_STRIDE (R + 4)

typedef unsigned long long u64;

// ---- packed f32x2 helpers (Blackwell FFMA2 pipe; ptxas never auto-emits) ----
__device__ __forceinline__ u64 ffma2(u64 a, u64 b, u64 c) {
    u64 d;
    asm("fma.rn.f32x2 %0, %1, %2, %3;" : "=l"(d) : "l"(a), "l"(b), "l"(c));
    return d;
}
__device__ __forceinline__ u64 fmul2(u64 a, u64 b) {
    u64 d;
    asm("mul.rn.f32x2 %0, %1, %2;" : "=l"(d) : "l"(a), "l"(b));
    return d;
}
__device__ __forceinline__ u64 pack2(float x, float y) {
    u64 r;
    asm("mov.b64 %0, {%1, %2};" : "=l"(r) : "f"(x), "f"(y));
    return r;
}
__device__ __forceinline__ float2 unpack2(u64 a) {
    float x, y;
    asm("mov.b64 {%0, %1}, %2;" : "=f"(x), "=f"(y) : "l"(a));
    return make_float2(x, y);
}

// scratch (allocation-free rule: device globals)
__device__ float g_z[R * DV];
__device__ float g_ksum[R];

__global__ void zero_kernel() {
    int t = blockIdx.x * blockDim.x + threadIdx.x;
    if (t < R * DV) g_z[t] = 0.0f;
    if (t < R) g_ksum[t] = 0.0f;
}

// ---------------- K side: z = k_hat^T @ v, ksum = sum_i k_hat[i,:] -------------
__global__ __launch_bounds__(256, 1) void kside_kernel(
    const float* __restrict__ kin, const float* __restrict__ vin,
    const float* __restrict__ proj)
{
    extern __shared__ float smem[];
    float* kn = smem;                      // ROWS_K * D
    float* vs = kn + ROWS_K * D;           // ROWS_K * DV
    float* sn = vs + ROWS_K * DV;          // ROWS_K

    const int t = threadIdx.x;             // 0..255 <-> feature r

    // projection row, packed pairs (32 x u64 = 64 floats)
    u64 pp[D / 2];
    {
        const ulonglong2* pg = reinterpret_cast<const ulonglong2*>(&proj[t * D]);
#pragma unroll
        for (int j = 0; j < D / 4; j++) {
            ulonglong2 w = pg[j];
            pp[2 * j] = w.x; pp[2 * j + 1] = w.y;
        }
    }

    u64 zacc2[DV / 2];
#pragma unroll
    for (int c = 0; c < DV / 2; c++) zacc2[c] = 0ull;
    float ksacc = 0.0f;

    for (int tile = blockIdx.x; tile < KTILES; tile += gridDim.x) {
        __syncthreads();
        const float4* kb = reinterpret_cast<const float4*>(kin + (size_t)tile * ROWS_K * D);
        const float4* vb = reinterpret_cast<const float4*>(vin + (size_t)tile * ROWS_K * DV);
#pragma unroll
        for (int m = 0; m < (ROWS_K * D / 4) / 256; m++) {   // 8 iters
            int idx = t + 256 * m;
            float4 a = kb[idx];
            a.x *= NORM; a.y *= NORM; a.z *= NORM; a.w *= NORM;
            *reinterpret_cast<float4*>(&kn[idx * 4]) = a;
            float ps = a.x * a.x + a.y * a.y + a.z * a.z + a.w * a.w;
#pragma unroll
            for (int s = 8; s >= 1; s >>= 1)
                ps += __shfl_xor_sync(0xffffffffu, ps, s);
            if ((t & 15) == 0) sn[idx >> 4] = ps;
            *reinterpret_cast<float4*>(&vs[idx * 4]) = vb[idx];
        }
        __syncthreads();

        for (int i = 0; i < ROWS_K; i++) {
            // dash = kn[i,:] . p  — packed, 2 accumulators to cover FMA latency
            u64 da = 0ull, db = 0ull;
            const ulonglong2* kr = reinterpret_cast<const ulonglong2*>(&kn[i * D]);
#pragma unroll
            for (int j = 0; j < D / 4; j++) {
                ulonglong2 w = kr[j];
                da = ffma2(w.x, pp[2 * j], da);
                db = ffma2(w.y, pp[2 * j + 1], db);
            }
            float2 fa = unpack2(da), fb = unpack2(db);
            float dash = (fa.x + fa.y) + (fb.x + fb.y);

            float kh = RATIO * __expf(dash - 0.5f * sn[i]);
            ksacc += kh;
            u64 kh2 = pack2(kh, kh);

            const ulonglong2* vr = reinterpret_cast<const ulonglong2*>(&vs[i * DV]);
#pragma unroll
            for (int c = 0; c < DV / 4; c++) {
                ulonglong2 w = vr[c];
                zacc2[2 * c]     = ffma2(kh2, w.x, zacc2[2 * c]);
                zacc2[2 * c + 1] = ffma2(kh2, w.y, zacc2[2 * c + 1]);
            }
        }
    }

    atomicAdd(&g_ksum[t], ksacc);
#pragma unroll
    for (int c = 0; c < DV / 2; c++) {
        float2 f = unpack2(zacc2[c]);
        atomicAdd(&g_z[t * DV + 2 * c],     f.x);
        atomicAdd(&g_z[t * DV + 2 * c + 1], f.y);
    }
}

// ---------------- Q side: out = (q_hat @ z) / (q_hat . ksum) ------------------
__global__ __launch_bounds__(256, 1) void qside_kernel(
    const float* __restrict__ qin, const float* __restrict__ proj,
    float* __restrict__ out)
{
    extern __shared__ float smem[];
    float* zsh  = smem;                          // R*DV
    float* qh   = zsh + R * DV;                  // ROWS_Q*QH_STRIDE
    float* qn   = qh + ROWS_Q * QH_STRIDE;       // ROWS_Q*D
    float* sn   = qn + ROWS_Q * D;               // ROWS_Q
    float* ks   = sn + ROWS_Q;                   // R
    float* dinv = ks + R;                        // ROWS_Q

    const int t = threadIdx.x;

    u64 pp[D / 2];
    {
        const ulonglong2* pg = reinterpret_cast<const ulonglong2*>(&proj[t * D]);
#pragma unroll
        for (int j = 0; j < D / 4; j++) {
            ulonglong2 w = pg[j];
            pp[2 * j] = w.x; pp[2 * j + 1] = w.y;
        }
    }

    // stage z + ksum into shared
#pragma unroll
    for (int m = 0; m < (R * DV / 4) / 256; m++) {   // 16 iters
        int idx = t + 256 * m;
        *reinterpret_cast<float4*>(&zsh[idx * 4]) =
            *reinterpret_cast<const float4*>(&g_z[idx * 4]);
    }
    ks[t] = g_ksum[t];

    const int tile = blockIdx.x;
    const float4* qb = reinterpret_cast<const float4*>(qin + (size_t)tile * ROWS_Q * D);
#pragma unroll
    for (int m = 0; m < (ROWS_Q * D / 4) / 256; m++) {  // 4 iters
        int idx = t + 256 * m;
        float4 a = qb[idx];
        a.x *= NORM; a.y *= NORM; a.z *= NORM; a.w *= NORM;
        *reinterpret_cast<float4*>(&qn[idx * 4]) = a;
        float ps = a.x * a.x + a.y * a.y + a.z * a.z + a.w * a.w;
#pragma unroll
        for (int s = 8; s >= 1; s >>= 1)
            ps += __shfl_xor_sync(0xffffffffu, ps, s);
        if ((t & 15) == 0) sn[idx >> 4] = ps;
    }
    __syncthreads();

    // phase 1: qh[i][t] = ratio * exp(dash - 0.5*sn)
    for (int i = 0; i < ROWS_Q; i++) {
        u64 da = 0ull, db = 0ull;
        const ulonglong2* qr = reinterpret_cast<const ulonglong2*>(&qn[i * D]);
#pragma unroll
        for (int j = 0; j < D / 4; j++) {
            ulonglong2 w = qr[j];
            da = ffma2(w.x, pp[2 * j], da);
            db = ffma2(w.y, pp[2 * j + 1], db);
        }
        float2 fa = unpack2(da), fb = unpack2(db);
        float dash = (fa.x + fa.y) + (fb.x + fb.y);
        qh[i * QH_STRIDE + t] = RATIO * __expf(dash - 0.5f * sn[i]);
    }
    __syncthreads();

    // denominators: warp w -> rows w*8 .. w*8+7
    {
        int w = t >> 5, l = t & 31;
#pragma unroll
        for (int ii = 0; ii < 8; ii++) {
            int i = w * 8 + ii;
            float s = 0.0f;
#pragma unroll
            for (int kk = 0; kk < R / 32; kk++)
                s += qh[i * QH_STRIDE + l + 32 * kk] * ks[l + 32 * kk];
#pragma unroll
            for (int sd = 16; sd >= 1; sd >>= 1)
                s += __shfl_xor_sync(0xffffffffu, s, sd);
            if (l == 0) dinv[i] = 1.0f / s;
        }
    }
    __syncthreads();

    // phase 2: 4x4 register-tiled GEMM qh[64x256] @ zsh[256x64], packed columns
    {
        const int bc = t & 15;       // column block
        const int bi = t >> 4;       // row block
        const int i0 = bi * 4;
        const int c0 = bc * 4;
        u64 acc[4][2];
#pragma unroll
        for (int a = 0; a < 4; a++) { acc[a][0] = 0ull; acc[a][1] = 0ull; }

#pragma unroll 4
        for (int r = 0; r < R; r++) {
            ulonglong2 zv = *reinterpret_cast<const ulonglong2*>(&zsh[r * DV + c0]);
            u64 q0 = pack2(qh[(i0 + 0) * QH_STRIDE + r], qh[(i0 + 0) * QH_STRIDE + r]);
            u64 q1 = pack2(qh[(i0 + 1) * QH_STRIDE + r], qh[(i0 + 1) * QH_STRIDE + r]);
            u64 q2 = pack2(qh[(i0 + 2) * QH_STRIDE + r], qh[(i0 + 2) * QH_STRIDE + r]);
            u64 q3 = pack2(qh[(i0 + 3) * QH_STRIDE + r], qh[(i0 + 3) * QH_STRIDE + r]);
            acc[0][0] = ffma2(q0, zv.x, acc[0][0]); acc[0][1] = ffma2(q0, zv.y, acc[0][1]);
            acc[1][0] = ffma2(q1, zv.x, acc[1][0]); acc[1][1] = ffma2(q1, zv.y, acc[1][1]);
            acc[2][0] = ffma2(q2, zv.x, acc[2][0]); acc[2][1] = ffma2(q2, zv.y, acc[2][1]);
            acc[3][0] = ffma2(q3, zv.x, acc[3][0]); acc[3][1] = ffma2(q3, zv.y, acc[3][1]);
        }

        float* ob = out + (size_t)tile * ROWS_Q * DV;
#pragma unroll
        for (int a = 0; a < 4; a++) {
            float di = dinv[i0 + a];
            u64 d2 = pack2(di, di);
            ulonglong2 o;
            o.x = fmul2(acc[a][0], d2);
            o.y = fmul2(acc[a][1], d2);
            *reinterpret_cast<ulonglong2*>(&ob[(i0 + a) * DV + c0]) = o;
        }
    }
}

extern "C" void kernel_launch(void* const* d_in, const int* in_sizes, int n_in,
                              void* d_out, int out_size) {
    const float* q = (const float*)d_in[0];
    const float* k = (const float*)d_in[1];
    const float* v = (const float*)d_in[2];
    const float* P = (const float*)d_in[3];
    float* out = (float*)d_out;
    (void)in_sizes; (void)n_in; (void)out_size;

    const int ksmem = (ROWS_K * D + ROWS_K * DV + ROWS_K) * (int)sizeof(float);
    const int qsmem = (R * DV + ROWS_Q * QH_STRIDE + ROWS_Q * D + ROWS_Q + R + ROWS_Q)
                      * (int)sizeof(float);

    cudaFuncSetAttribute(kside_kernel, cudaFuncAttributeMaxDynamicSharedMemorySize, ksmem);
    cudaFuncSetAttribute(qside_kernel, cudaFuncAttributeMaxDynamicSharedMemorySize, qsmem);

    zero_kernel<<<64, 256>>>();
    kside_kernel<<<KBLOCKS, 256, ksmem>>>(k, v, P);
    qside_kernel<<<QTILES, 256, qsmem>>>(q, P, out);
}